// round 1
// baseline (speedup 1.0000x reference)
#include <cuda_runtime.h>
#include <math.h>

#define B_   2
#define S_   2048
#define C_   1024
#define H_   16
#define DH_  64
#define M_   (B_ * S_)       // 4096 rows

// ---- scratch (device globals; no allocation allowed) ----
__device__ float g_Q[M_ * C_];
__device__ float g_K[M_ * C_];
__device__ float g_V[M_ * C_];
__device__ float g_A[M_ * C_];           // attention output (pre out-proj)
__device__ float g_m1[B_ * H_ * S_];     // full-row max of scores (already /8)
__device__ float g_vs[B_ * H_ * DH_];    // sum over all keys of V per (b,h)

// ============================================================================
// 128x128x8 double-buffered SGEMM: C = A[M,K] @ B[K,N]. M,N,K multiples of 128.
// ============================================================================
__global__ __launch_bounds__(256) void sgemm128(
    const float* __restrict__ A, const float* __restrict__ B,
    float* __restrict__ C, int M, int N, int K)
{
    __shared__ float As[2][8][128];
    __shared__ float Bs[2][8][128];

    const int tid = threadIdx.x;
    const int bm = blockIdx.y * 128;
    const int bn = blockIdx.x * 128;

    const int a_row = tid >> 1;          // 0..127
    const int a_k   = (tid & 1) * 4;     // 0 or 4
    const int b_r   = tid >> 5;          // 0..7
    const int b_c   = (tid & 31) * 4;    // 0..124

    const int ty = tid >> 4;             // 0..15
    const int tx = tid & 15;             // 0..15

    const float* Ap = A + (bm + a_row) * K + a_k;
    const float* Bp = B + b_r * N + bn + b_c;

    float acc[8][8];
#pragma unroll
    for (int i = 0; i < 8; ++i)
#pragma unroll
        for (int j = 0; j < 8; ++j) acc[i][j] = 0.f;

    float4 av = *(const float4*)Ap;
    float4 bv = *(const float4*)Bp;
    As[0][a_k + 0][a_row] = av.x;
    As[0][a_k + 1][a_row] = av.y;
    As[0][a_k + 2][a_row] = av.z;
    As[0][a_k + 3][a_row] = av.w;
    *(float4*)&Bs[0][b_r][b_c] = bv;
    __syncthreads();

    const int nt = K >> 3;
    int buf = 0;
    for (int t = 0; t < nt; ++t) {
        if (t + 1 < nt) {
            av = *(const float4*)(Ap + (t + 1) * 8);
            bv = *(const float4*)(Bp + (t + 1) * 8 * N);
        }
#pragma unroll
        for (int kk = 0; kk < 8; ++kk) {
            float a[8], b[8];
            *(float4*)&a[0] = *(const float4*)&As[buf][kk][ty * 8];
            *(float4*)&a[4] = *(const float4*)&As[buf][kk][ty * 8 + 4];
            *(float4*)&b[0] = *(const float4*)&Bs[buf][kk][tx * 8];
            *(float4*)&b[4] = *(const float4*)&Bs[buf][kk][tx * 8 + 4];
#pragma unroll
            for (int i = 0; i < 8; ++i)
#pragma unroll
                for (int j = 0; j < 8; ++j)
                    acc[i][j] = fmaf(a[i], b[j], acc[i][j]);
        }
        if (t + 1 < nt) {
            buf ^= 1;
            As[buf][a_k + 0][a_row] = av.x;
            As[buf][a_k + 1][a_row] = av.y;
            As[buf][a_k + 2][a_row] = av.z;
            As[buf][a_k + 3][a_row] = av.w;
            *(float4*)&Bs[buf][b_r][b_c] = bv;
        }
        __syncthreads();
    }

#pragma unroll
    for (int i = 0; i < 8; ++i) {
        float* cp = C + (bm + ty * 8 + i) * N + bn + tx * 8;
        float4 o0 = make_float4(acc[i][0], acc[i][1], acc[i][2], acc[i][3]);
        float4 o1 = make_float4(acc[i][4], acc[i][5], acc[i][6], acc[i][7]);
        *(float4*)cp = o0;
        *(float4*)(cp + 4) = o1;
    }
}

// ============================================================================
// Full-row score max: m1[bh][q] = max_k (q . k) / 8 over all 2048 keys.
// Block: 128 queries of one (b,h); GEMM-shaped inner loop with 64-key tiles.
// ============================================================================
__global__ __launch_bounds__(256) void score_max(
    const float* __restrict__ Q, const float* __restrict__ K,
    float* __restrict__ m1)
{
    __shared__ float Qs[64][128];   // [d][q]  32KB
    __shared__ float Ks[64][64];    // [d][k]  16KB

    const int bh = blockIdx.y;
    const int b = bh >> 4, h = bh & 15;
    const int q0 = blockIdx.x * 128;
    const int tid = threadIdx.x;
    const int rowbase = (b * S_) * C_ + h * DH_;

    // load+transpose Q tile (128q x 64d)
#pragma unroll
    for (int u = 0; u < 8; ++u) {
        int f = tid + 256 * u;              // 0..2047 float4 slots
        int qq = f >> 4;                    // 0..127
        int d4 = (f & 15) * 4;
        float4 v = *(const float4*)(Q + rowbase + (q0 + qq) * C_ + d4);
        Qs[d4 + 0][qq] = v.x;
        Qs[d4 + 1][qq] = v.y;
        Qs[d4 + 2][qq] = v.z;
        Qs[d4 + 3][qq] = v.w;
    }

    const int qy = tid >> 3;   // 0..31 -> queries qy*4 .. +3
    const int kx = tid & 7;    // 0..7  -> keys    kx*8 .. +7
    float rmax[4] = { -1e30f, -1e30f, -1e30f, -1e30f };

    for (int kt = 0; kt < S_; kt += 64) {
        __syncthreads();   // prev compute done (and Q stores visible on iter 0)
#pragma unroll
        for (int u = 0; u < 4; ++u) {
            int f = tid + 256 * u;          // 0..1023
            int kk = f >> 4;                // 0..63
            int d4 = (f & 15) * 4;
            float4 v = *(const float4*)(K + rowbase + (kt + kk) * C_ + d4);
            Ks[d4 + 0][kk] = v.x;
            Ks[d4 + 1][kk] = v.y;
            Ks[d4 + 2][kk] = v.z;
            Ks[d4 + 3][kk] = v.w;
        }
        __syncthreads();

        float acc[4][8];
#pragma unroll
        for (int i = 0; i < 4; ++i)
#pragma unroll
            for (int j = 0; j < 8; ++j) acc[i][j] = 0.f;

#pragma unroll 16
        for (int dd = 0; dd < 64; ++dd) {
            float a[4], bb[8];
            *(float4*)&a[0]  = *(const float4*)&Qs[dd][qy * 4];
            *(float4*)&bb[0] = *(const float4*)&Ks[dd][kx * 8];
            *(float4*)&bb[4] = *(const float4*)&Ks[dd][kx * 8 + 4];
#pragma unroll
            for (int i = 0; i < 4; ++i)
#pragma unroll
                for (int j = 0; j < 8; ++j)
                    acc[i][j] = fmaf(a[i], bb[j], acc[i][j]);
        }
#pragma unroll
        for (int i = 0; i < 4; ++i)
#pragma unroll
            for (int j = 0; j < 8; ++j)
                rmax[i] = fmaxf(rmax[i], acc[i][j]);
    }

    // reduce over the 8 kx lanes (contiguous within a warp)
#pragma unroll
    for (int off = 4; off; off >>= 1)
#pragma unroll
        for (int i = 0; i < 4; ++i)
            rmax[i] = fmaxf(rmax[i], __shfl_xor_sync(0xffffffffu, rmax[i], off));

    if (kx == 0) {
#pragma unroll
        for (int i = 0; i < 4; ++i)
            m1[bh * S_ + q0 + qy * 4 + i] = rmax[i] * 0.125f;
    }
}

// ============================================================================
// V column sums per (b,h): vs[bh][d] = sum_k V[k][d]
// ============================================================================
__global__ __launch_bounds__(256) void vsum_k(
    const float* __restrict__ V, float* __restrict__ vs)
{
    __shared__ float red[4][64];
    const int bh = blockIdx.x;
    const int b = bh >> 4, h = bh & 15;
    const int tid = threadIdx.x;
    const int d = tid & 63, g = tid >> 6;
    const float* p = V + (b * S_) * C_ + h * DH_ + d;
    float s = 0.f;
    for (int k = g; k < S_; k += 4) s += p[k * C_];
    red[g][d] = s;
    __syncthreads();
    if (tid < 64)
        vs[bh * 64 + tid] = red[0][tid] + red[1][tid] + red[2][tid] + red[3][tid];
}

// ============================================================================
// Banded attention:
// out[q] = (sum_band (e^{t}-1) v + vsum) / (S + sum_band (e^{t}-1)),
// t = exp(s/8 - m1_q). One thread per query, 128 queries/block.
// ============================================================================
__global__ __launch_bounds__(128) void band_attn(
    const float* __restrict__ Q, const float* __restrict__ K,
    const float* __restrict__ V, const float* __restrict__ m1,
    const float* __restrict__ vs, float* __restrict__ O)
{
    __shared__ float Ks[64][64];
    __shared__ float Vs[64][64];

    const int bh = blockIdx.y;
    const int b = bh >> 4, h = bh & 15;
    const int q0 = blockIdx.x * 128;
    const int tid = threadIdx.x;
    const int q = q0 + tid;
    const int rowbase = (b * S_) * C_ + h * DH_;

    float qv[64];
#pragma unroll
    for (int d = 0; d < 64; d += 4) {
        float4 t = *(const float4*)(Q + rowbase + q * C_ + d);
        qv[d] = t.x; qv[d + 1] = t.y; qv[d + 2] = t.z; qv[d + 3] = t.w;
    }
    const float m1q = m1[bh * S_ + q];

    float acc[64];
#pragma unroll
    for (int d = 0; d < 64; ++d) acc[d] = 0.f;
    float Z = 0.f;

    const int klo  = (q0 - 128 > 0) ? q0 - 128 : 0;        // 64-aligned
    const int kend = (q0 + 256 < S_) ? q0 + 256 : S_;

    for (int kt = klo; kt < kend; kt += 64) {
        __syncthreads();
#pragma unroll
        for (int u = 0; u < 8; ++u) {
            int f = tid + 128 * u;      // 0..1023 float4 slots
            int key = f >> 4;           // 0..63
            int d4 = (f & 15) * 4;
            int g = rowbase + (kt + key) * C_ + d4;
            *(float4*)&Ks[key][d4] = *(const float4*)(K + g);
            *(float4*)&Vs[key][d4] = *(const float4*)(V + g);
        }
        __syncthreads();

        int lob = q - 128; if (lob < kt) lob = kt; if (lob < 0) lob = 0;
        int hib = q + 128; if (hib > kt + 64) hib = kt + 64; if (hib > S_) hib = S_;
        for (int kk = lob - kt; kk < hib - kt; ++kk) {
            float s = 0.f;
#pragma unroll
            for (int d4 = 0; d4 < 64; d4 += 4) {
                float4 kv = *(const float4*)&Ks[kk][d4];
                s = fmaf(qv[d4 + 0], kv.x, s);
                s = fmaf(qv[d4 + 1], kv.y, s);
                s = fmaf(qv[d4 + 2], kv.z, s);
                s = fmaf(qv[d4 + 3], kv.w, s);
            }
            float t = __expf(s * 0.125f - m1q);   // in (0,1]
            float w = __expf(t) - 1.0f;           // in (0, e-1]
            Z += w;
#pragma unroll
            for (int d4 = 0; d4 < 64; d4 += 4) {
                float4 vv = *(const float4*)&Vs[kk][d4];
                acc[d4 + 0] = fmaf(w, vv.x, acc[d4 + 0]);
                acc[d4 + 1] = fmaf(w, vv.y, acc[d4 + 1]);
                acc[d4 + 2] = fmaf(w, vv.z, acc[d4 + 2]);
                acc[d4 + 3] = fmaf(w, vv.w, acc[d4 + 3]);
            }
        }
    }

    const float inv = 1.0f / ((float)S_ + Z);
#pragma unroll
    for (int d = 0; d < 64; d += 4) {
        float4 vv = *(const float4*)(vs + bh * 64 + d);
        float4 o;
        o.x = (acc[d + 0] + vv.x) * inv;
        o.y = (acc[d + 1] + vv.y) * inv;
        o.z = (acc[d + 2] + vv.z) * inv;
        o.w = (acc[d + 3] + vv.w) * inv;
        *(float4*)(O + rowbase + q * C_ + d) = o;
    }
}

// ============================================================================
extern "C" void kernel_launch(void* const* d_in, const int* in_sizes, int n_in,
                              void* d_out, int out_size)
{
    (void)in_sizes; (void)n_in; (void)out_size;
    const float* x  = (const float*)d_in[0];
    const float* Wq = (const float*)d_in[1];
    const float* Wk = (const float*)d_in[2];
    const float* Wv = (const float*)d_in[3];
    const float* Wo = (const float*)d_in[4];
    float* out = (float*)d_out;

    float *Qp, *Kp, *Vp, *Ap, *m1p, *vsp;
    cudaGetSymbolAddress((void**)&Qp,  g_Q);
    cudaGetSymbolAddress((void**)&Kp,  g_K);
    cudaGetSymbolAddress((void**)&Vp,  g_V);
    cudaGetSymbolAddress((void**)&Ap,  g_A);
    cudaGetSymbolAddress((void**)&m1p, g_m1);
    cudaGetSymbolAddress((void**)&vsp, g_vs);

    dim3 gg(C_ / 128, M_ / 128);            // (8, 32)
    sgemm128<<<gg, 256>>>(x, Wq, Qp, M_, C_, C_);
    sgemm128<<<gg, 256>>>(x, Wk, Kp, M_, C_, C_);
    sgemm128<<<gg, 256>>>(x, Wv, Vp, M_, C_, C_);

    score_max<<<dim3(S_ / 128, B_ * H_), 256>>>(Qp, Kp, m1p);
    vsum_k<<<B_ * H_, 256>>>(Vp, vsp);
    band_attn<<<dim3(S_ / 128, B_ * H_), 128>>>(Qp, Kp, Vp, m1p, vsp, Ap);

    sgemm128<<<gg, 256>>>(Ap, Wo, out, M_, C_, C_);
}

// round 2
// speedup vs baseline: 1.3750x; 1.3750x over previous
#include <cuda_runtime.h>
#include <math.h>

#define B_   2
#define S_   2048
#define C_   1024
#define H_   16
#define DH_  64
#define M_   (B_ * S_)       // 4096 rows

// ---- scratch (device globals; no allocation allowed) ----
__device__ float g_Q[M_ * C_];
__device__ float g_K[M_ * C_];
__device__ float g_V[M_ * C_];
__device__ float g_A[M_ * C_];           // attention output (pre out-proj)
__device__ float g_m1[B_ * H_ * S_];     // full-row max of scores (already /8)
__device__ float g_vs[B_ * H_ * DH_];    // sum over all keys of V per (b,h)

// ============================================================================
// 128x128x8 double-buffered SGEMM: C = A[M,K] @ B[K,N]. M,N,K multiples of 128.
// Conflict-free b-loads via split columns (tx*4 and 64+tx*4).
// ============================================================================
__global__ __launch_bounds__(256) void sgemm128(
    const float* __restrict__ A, const float* __restrict__ B,
    float* __restrict__ C, int M, int N, int K)
{
    __shared__ float As[2][8][128];
    __shared__ float Bs[2][8][128];

    const int tid = threadIdx.x;
    const int bm = blockIdx.y * 128;
    const int bn = blockIdx.x * 128;

    const int a_row = tid >> 1;          // 0..127
    const int a_k   = (tid & 1) * 4;     // 0 or 4
    const int b_r   = tid >> 5;          // 0..7
    const int b_c   = (tid & 31) * 4;    // 0..124

    const int ty = tid >> 4;             // 0..15
    const int tx = tid & 15;             // 0..15

    const float* Ap = A + (bm + a_row) * K + a_k;
    const float* Bp = B + b_r * N + bn + b_c;

    float acc[8][8];
#pragma unroll
    for (int i = 0; i < 8; ++i)
#pragma unroll
        for (int j = 0; j < 8; ++j) acc[i][j] = 0.f;

    float4 av = *(const float4*)Ap;
    float4 bv = *(const float4*)Bp;
    As[0][a_k + 0][a_row] = av.x;
    As[0][a_k + 1][a_row] = av.y;
    As[0][a_k + 2][a_row] = av.z;
    As[0][a_k + 3][a_row] = av.w;
    *(float4*)&Bs[0][b_r][b_c] = bv;
    __syncthreads();

    const int nt = K >> 3;
    int buf = 0;
    for (int t = 0; t < nt; ++t) {
        if (t + 1 < nt) {
            av = *(const float4*)(Ap + (t + 1) * 8);
            bv = *(const float4*)(Bp + (t + 1) * 8 * N);
        }
#pragma unroll
        for (int kk = 0; kk < 8; ++kk) {
            float a[8], b[8];
            *(float4*)&a[0] = *(const float4*)&As[buf][kk][ty * 8];
            *(float4*)&a[4] = *(const float4*)&As[buf][kk][ty * 8 + 4];
            *(float4*)&b[0] = *(const float4*)&Bs[buf][kk][tx * 4];
            *(float4*)&b[4] = *(const float4*)&Bs[buf][kk][tx * 4 + 64];
#pragma unroll
            for (int i = 0; i < 8; ++i)
#pragma unroll
                for (int j = 0; j < 8; ++j)
                    acc[i][j] = fmaf(a[i], b[j], acc[i][j]);
        }
        if (t + 1 < nt) {
            buf ^= 1;
            As[buf][a_k + 0][a_row] = av.x;
            As[buf][a_k + 1][a_row] = av.y;
            As[buf][a_k + 2][a_row] = av.z;
            As[buf][a_k + 3][a_row] = av.w;
            *(float4*)&Bs[buf][b_r][b_c] = bv;
        }
        __syncthreads();
    }

#pragma unroll
    for (int i = 0; i < 8; ++i) {
        float* cp = C + (bm + ty * 8 + i) * N + bn;
        *(float4*)(cp + tx * 4)      = make_float4(acc[i][0], acc[i][1], acc[i][2], acc[i][3]);
        *(float4*)(cp + 64 + tx * 4) = make_float4(acc[i][4], acc[i][5], acc[i][6], acc[i][7]);
    }
}

// ============================================================================
// Full-row score max: m1[bh][q] = max_k (q . k) / 8 over all 2048 keys.
// 128q x 128k tiles, 8x8 per-thread blocking, dh split into 2 chunks of 32
// so smem stays at 48KB static. Conflict-free LDS throughout.
// ============================================================================
__global__ __launch_bounds__(256, 2) void score_max(
    const float* __restrict__ Q, const float* __restrict__ K,
    float* __restrict__ m1)
{
    __shared__ float Qs[64][128];   // [d][q]  32KB (loaded once)
    __shared__ float Ks[32][128];   // [d-half][k] 16KB (reloaded per chunk)

    const int bh = blockIdx.y;
    const int b = bh >> 4, h = bh & 15;
    const int q0 = blockIdx.x * 128;
    const int tid = threadIdx.x;
    const int rowbase = (b * S_) * C_ + h * DH_;

    // load+transpose Q tile (128q x 64d) -> Qs[d][q]
#pragma unroll
    for (int u = 0; u < 8; ++u) {
        int f = tid + 256 * u;              // 0..2047 float4 slots
        int qq = f & 127;
        int d4 = (f >> 7) * 4;              // 0..60
        float4 v = *(const float4*)(Q + rowbase + (q0 + qq) * C_ + d4);
        Qs[d4 + 0][qq] = v.x;
        Qs[d4 + 1][qq] = v.y;
        Qs[d4 + 2][qq] = v.z;
        Qs[d4 + 3][qq] = v.w;
    }

    const int ty = tid >> 4;   // 0..15 -> queries ty*8 .. +7
    const int tx = tid & 15;   // 0..15 -> keys tx*4..+3 and 64+tx*4..+3

    float rmax[8];
#pragma unroll
    for (int i = 0; i < 8; ++i) rmax[i] = -1e30f;

    for (int kt = 0; kt < S_; kt += 128) {
        float acc[8][8];
#pragma unroll
        for (int i = 0; i < 8; ++i)
#pragma unroll
            for (int j = 0; j < 8; ++j) acc[i][j] = 0.f;

#pragma unroll
        for (int ch = 0; ch < 2; ++ch) {
            __syncthreads();   // prev compute done (and Qs visible on iter 0)
#pragma unroll
            for (int u = 0; u < 4; ++u) {
                int f = tid + 256 * u;          // 0..1023 float4 slots
                int kk = f & 127;
                int d4 = (f >> 7) * 4;          // 0..28
                float4 v = *(const float4*)(K + rowbase + (kt + kk) * C_ + ch * 32 + d4);
                Ks[d4 + 0][kk] = v.x;
                Ks[d4 + 1][kk] = v.y;
                Ks[d4 + 2][kk] = v.z;
                Ks[d4 + 3][kk] = v.w;
            }
            __syncthreads();

#pragma unroll
            for (int dd = 0; dd < 32; ++dd) {
                float a[8], bb[8];
                *(float4*)&a[0]  = *(const float4*)&Qs[ch * 32 + dd][ty * 8];
                *(float4*)&a[4]  = *(const float4*)&Qs[ch * 32 + dd][ty * 8 + 4];
                *(float4*)&bb[0] = *(const float4*)&Ks[dd][tx * 4];
                *(float4*)&bb[4] = *(const float4*)&Ks[dd][tx * 4 + 64];
#pragma unroll
                for (int i = 0; i < 8; ++i)
#pragma unroll
                    for (int j = 0; j < 8; ++j)
                        acc[i][j] = fmaf(a[i], bb[j], acc[i][j]);
            }
        }

#pragma unroll
        for (int i = 0; i < 8; ++i)
#pragma unroll
            for (int j = 0; j < 8; ++j)
                rmax[i] = fmaxf(rmax[i], acc[i][j]);
    }

    // reduce over the 16 tx lanes (xor offsets < 16 stay within the group)
#pragma unroll
    for (int off = 8; off; off >>= 1)
#pragma unroll
        for (int i = 0; i < 8; ++i)
            rmax[i] = fmaxf(rmax[i], __shfl_xor_sync(0xffffffffu, rmax[i], off));

    if (tx == 0) {
#pragma unroll
        for (int i = 0; i < 8; ++i)
            m1[bh * S_ + q0 + ty * 8 + i] = rmax[i] * 0.125f;
    }
}

// ============================================================================
// V column sums per (b,h): vs[bh][d] = sum_k V[k][d]
// ============================================================================
__global__ __launch_bounds__(256) void vsum_k(
    const float* __restrict__ V, float* __restrict__ vs)
{
    __shared__ float red[4][64];
    const int bh = blockIdx.x;
    const int b = bh >> 4, h = bh & 15;
    const int tid = threadIdx.x;
    const int d = tid & 63, g = tid >> 6;
    const float* p = V + (b * S_) * C_ + h * DH_ + d;
    float s = 0.f;
    for (int k = g; k < S_; k += 4) s += p[k * C_];
    red[g][d] = s;
    __syncthreads();
    if (tid < 64)
        vs[bh * 64 + tid] = red[0][tid] + red[1][tid] + red[2][tid] + red[3][tid];
}

// ============================================================================
// Banded attention, 2 threads per query (d-split), predicated band weight.
// out[q] = (sum_band (e^{t}-1) v + vsum) / (S + sum_band (e^{t}-1)),
// t = exp(s/8 - m1_q). All smem K/V reads are warp broadcasts.
// ============================================================================
__global__ __launch_bounds__(128) void band_attn(
    const float* __restrict__ Q, const float* __restrict__ K,
    const float* __restrict__ V, const float* __restrict__ m1,
    const float* __restrict__ vs, float* __restrict__ O)
{
    __shared__ float Ks[64][64];
    __shared__ float Vs[64][64];

    const int bh = blockIdx.y;
    const int b = bh >> 4, h = bh & 15;
    const int q0 = blockIdx.x * 64;
    const int tid = threadIdx.x;
    const int qi = tid >> 1;        // 0..63
    const int ht = tid & 1;         // d-half
    const int q = q0 + qi;
    const int rowbase = (b * S_) * C_ + h * DH_;

    float qv[32];
    const float* qptr = Q + rowbase + q * C_ + ht * 32;
#pragma unroll
    for (int j = 0; j < 32; j += 4)
        *(float4*)&qv[j] = *(const float4*)(qptr + j);

    const float m1q = m1[bh * S_ + q];

    float acc[32];
#pragma unroll
    for (int j = 0; j < 32; ++j) acc[j] = 0.f;
    float Z = 0.f;

    const int klo  = (q0 >= 128) ? q0 - 128 : 0;       // 64-aligned
    const int kend = (q0 + 192 < S_) ? q0 + 192 : S_;

    for (int kt = klo; kt < kend; kt += 64) {
        __syncthreads();
#pragma unroll
        for (int u = 0; u < 8; ++u) {
            int f = tid + 128 * u;      // 0..1023 float4 slots
            int kk = f >> 4;            // 0..63
            int d4 = (f & 15) * 4;
            int g = rowbase + (kt + kk) * C_ + d4;
            *(float4*)&Ks[kk][d4] = *(const float4*)(K + g);
            *(float4*)&Vs[kk][d4] = *(const float4*)(V + g);
        }
        __syncthreads();

#pragma unroll 4
        for (int kk = 0; kk < 64; ++kk) {
            float s = 0.f;
#pragma unroll
            for (int j = 0; j < 32; j += 4) {
                float4 kv = *(const float4*)&Ks[kk][ht * 32 + j];
                s = fmaf(qv[j + 0], kv.x, s);
                s = fmaf(qv[j + 1], kv.y, s);
                s = fmaf(qv[j + 2], kv.z, s);
                s = fmaf(qv[j + 3], kv.w, s);
            }
            s += __shfl_xor_sync(0xffffffffu, s, 1);
            float t = __expf(s * 0.125f - m1q);   // t in (0,1], no overflow
            float w = __expf(t) - 1.0f;
            int d = kt + kk - q;
            if (d < -128 || d > 127) w = 0.f;     // outside band
            Z += w;
#pragma unroll
            for (int j = 0; j < 32; j += 4) {
                float4 vv = *(const float4*)&Vs[kk][ht * 32 + j];
                acc[j + 0] = fmaf(w, vv.x, acc[j + 0]);
                acc[j + 1] = fmaf(w, vv.y, acc[j + 1]);
                acc[j + 2] = fmaf(w, vv.z, acc[j + 2]);
                acc[j + 3] = fmaf(w, vv.w, acc[j + 3]);
            }
        }
    }

    const float inv = 1.0f / ((float)S_ + Z);
    const float* vsp = vs + bh * 64 + ht * 32;
    float* op = O + rowbase + q * C_ + ht * 32;
#pragma unroll
    for (int j = 0; j < 32; j += 4) {
        float4 vv = *(const float4*)(vsp + j);
        float4 o;
        o.x = (acc[j + 0] + vv.x) * inv;
        o.y = (acc[j + 1] + vv.y) * inv;
        o.z = (acc[j + 2] + vv.z) * inv;
        o.w = (acc[j + 3] + vv.w) * inv;
        *(float4*)(op + j) = o;
    }
}

// ============================================================================
extern "C" void kernel_launch(void* const* d_in, const int* in_sizes, int n_in,
                              void* d_out, int out_size)
{
    (void)in_sizes; (void)n_in; (void)out_size;
    const float* x  = (const float*)d_in[0];
    const float* Wq = (const float*)d_in[1];
    const float* Wk = (const float*)d_in[2];
    const float* Wv = (const float*)d_in[3];
    const float* Wo = (const float*)d_in[4];
    float* out = (float*)d_out;

    float *Qp, *Kp, *Vp, *Ap, *m1p, *vsp;
    cudaGetSymbolAddress((void**)&Qp,  g_Q);
    cudaGetSymbolAddress((void**)&Kp,  g_K);
    cudaGetSymbolAddress((void**)&Vp,  g_V);
    cudaGetSymbolAddress((void**)&Ap,  g_A);
    cudaGetSymbolAddress((void**)&m1p, g_m1);
    cudaGetSymbolAddress((void**)&vsp, g_vs);

    dim3 gg(C_ / 128, M_ / 128);            // (8, 32)
    sgemm128<<<gg, 256>>>(x, Wq, Qp, M_, C_, C_);
    sgemm128<<<gg, 256>>>(x, Wk, Kp, M_, C_, C_);
    sgemm128<<<gg, 256>>>(x, Wv, Vp, M_, C_, C_);

    score_max<<<dim3(S_ / 128, B_ * H_), 256>>>(Qp, Kp, m1p);
    vsum_k<<<B_ * H_, 256>>>(Vp, vsp);
    band_attn<<<dim3(S_ / 64, B_ * H_), 128>>>(Qp, Kp, Vp, m1p, vsp, Ap);

    sgemm128<<<gg, 256>>>(Ap, Wo, out, M_, C_, C_);
}

// round 3
// speedup vs baseline: 1.9735x; 1.4353x over previous
#include <cuda_runtime.h>
#include <math.h>

#define B_   2
#define S_   2048
#define C_   1024
#define H_   16
#define DH_  64
#define M_   (B_ * S_)       // 4096 rows

// ---- scratch (device globals; no allocation allowed) ----
__device__ float g_Q[M_ * C_];
__device__ float g_K[M_ * C_];
__device__ float g_V[M_ * C_];
__device__ float g_A[M_ * C_];           // attention output (pre out-proj)
__device__ float g_m1[B_ * H_ * S_];     // full-row max of scores (already /8)
__device__ float g_vs[B_ * H_ * DH_];    // sum over all keys of V per (b,h)

__device__ __forceinline__ unsigned f2tf(float x) {
    unsigned r;
    asm("cvt.rna.tf32.f32 %0, %1;" : "=r"(r) : "f"(x));
    return r;
}

#define MMA_TF32(c, a, b)                                                     \
    asm volatile(                                                             \
        "mma.sync.aligned.m16n8k8.row.col.f32.tf32.tf32.f32 "                 \
        "{%0,%1,%2,%3},{%4,%5,%6,%7},{%8,%9},{%0,%1,%2,%3};"                  \
        : "+f"((c)[0]), "+f"((c)[1]), "+f"((c)[2]), "+f"((c)[3])              \
        : "r"((a)[0]), "r"((a)[1]), "r"((a)[2]), "r"((a)[3]),                 \
          "r"((b)[0]), "r"((b)[1]))

// ============================================================================
// tf32 tensor-core GEMM: C = A[M,K] @ B[K,N], 128x128x32 block tile,
// 8 warps (4x2), warp tile 32x64 (2 m-atoms x 8 n-atoms of m16n8k8).
// Conflict-free fragment LDS via pad: bank = (4m+k)%32 / (4k+n)%32.
// ============================================================================
__global__ __launch_bounds__(256) void tgemm(
    const float* __restrict__ A, const float* __restrict__ Bm,
    float* __restrict__ C, int M, int N, int K)
{
    __shared__ unsigned As[128][36];   // [m][k] tf32
    __shared__ unsigned Bs[32][132];   // [k][n] tf32

    const int tid = threadIdx.x;
    const int bm = blockIdx.y * 128;
    const int bn = blockIdx.x * 128;

    const int wid  = tid >> 5;
    const int lane = tid & 31;
    const int g    = lane >> 2;      // groupID 0..7
    const int tig  = lane & 3;       // thread-in-group 0..3
    const int warpM = wid >> 1;      // 0..3
    const int warpN = wid & 1;       // 0..1

    // global load assignment
    const int a_m  = tid >> 1;                 // 0..127
    const int a_k0 = (tid & 1) * 16;           // 0 or 16
    const int b_k  = tid >> 3;                 // 0..31
    const int b_n0 = (tid & 7) * 16;           // 0..112

    const float* Ap = A + (bm + a_m) * K + a_k0;
    const float* Bp = Bm + b_k * N + bn + b_n0;

    float c[2][8][4];
#pragma unroll
    for (int i = 0; i < 2; ++i)
#pragma unroll
        for (int j = 0; j < 8; ++j)
#pragma unroll
            for (int r = 0; r < 4; ++r) c[i][j][r] = 0.f;

    float4 av[4], bv[4];
#pragma unroll
    for (int j = 0; j < 4; ++j) {
        av[j] = *(const float4*)(Ap + j * 4);
        bv[j] = *(const float4*)(Bp + j * 4);
    }

    for (int kt = 0; kt < K; kt += 32) {
        // store staged regs to smem (tf32)
#pragma unroll
        for (int j = 0; j < 4; ++j) {
            uint4 ta, tb;
            ta.x = f2tf(av[j].x); ta.y = f2tf(av[j].y);
            ta.z = f2tf(av[j].z); ta.w = f2tf(av[j].w);
            tb.x = f2tf(bv[j].x); tb.y = f2tf(bv[j].y);
            tb.z = f2tf(bv[j].z); tb.w = f2tf(bv[j].w);
            *(uint4*)&As[a_m][a_k0 + j * 4] = ta;
            *(uint4*)&Bs[b_k][b_n0 + j * 4] = tb;
        }
        __syncthreads();

        if (kt + 32 < K) {
#pragma unroll
            for (int j = 0; j < 4; ++j) {
                av[j] = *(const float4*)(Ap + kt + 32 + j * 4);
                bv[j] = *(const float4*)(Bp + (kt + 32) * N + j * 4);
            }
        }

#pragma unroll
        for (int ks = 0; ks < 4; ++ks) {
            const int k0 = ks * 8;
            unsigned a[2][4];
#pragma unroll
            for (int m2 = 0; m2 < 2; ++m2) {
                const int mr = warpM * 32 + m2 * 16;
                a[m2][0] = As[mr + g][k0 + tig];
                a[m2][1] = As[mr + g + 8][k0 + tig];
                a[m2][2] = As[mr + g][k0 + tig + 4];
                a[m2][3] = As[mr + g + 8][k0 + tig + 4];
            }
#pragma unroll
            for (int j = 0; j < 8; ++j) {
                unsigned b[2];
                const int nc = warpN * 64 + j * 8 + g;
                b[0] = Bs[k0 + tig][nc];
                b[1] = Bs[k0 + tig + 4][nc];
                MMA_TF32(c[0][j], a[0], b);
                MMA_TF32(c[1][j], a[1], b);
            }
        }
        __syncthreads();
    }

#pragma unroll
    for (int m2 = 0; m2 < 2; ++m2) {
#pragma unroll
        for (int j = 0; j < 8; ++j) {
            const int row = bm + warpM * 32 + m2 * 16 + g;
            const int col = bn + warpN * 64 + j * 8 + 2 * tig;
            *(float2*)&C[row * N + col]       = make_float2(c[m2][j][0], c[m2][j][1]);
            *(float2*)&C[(row + 8) * N + col] = make_float2(c[m2][j][2], c[m2][j][3]);
        }
    }
}

// ============================================================================
// tf32 tensor-core score max: m1[bh][q] = max_k (q.k)/8 over all 2048 keys.
// Block: 64 queries of one (b,h). Q tile in smem (loaded once, [m][k]),
// K^T tiles streamed ([k][n], 64 keys per tile). 8 warps: warpM=wid&1 (32 q),
// warpN=wid>>2?? -> warpN=wid>>1 (0..3, 16 keys each), 2x2 atoms, 8 ksteps.
// ============================================================================
__global__ __launch_bounds__(256) void score_max_t(
    const float* __restrict__ Q, const float* __restrict__ K,
    float* __restrict__ m1)
{
    __shared__ unsigned Qs[64][68];    // [q][d] tf32, 17.4KB
    __shared__ unsigned Ks[64][68];    // [d][key] tf32 (transposed), 17.4KB
    __shared__ float buf[4][64];

    const int bh = blockIdx.y;
    const int b = bh >> 4, h = bh & 15;
    const int q0 = blockIdx.x * 64;
    const int tid = threadIdx.x;
    const int rowbase = (b * S_) * C_ + h * DH_;

    const int wid  = tid >> 5;
    const int lane = tid & 31;
    const int g    = lane >> 2;
    const int tig  = lane & 3;
    const int warpM = wid & 1;       // 0..1 -> 32 query rows
    const int warpN = wid >> 1;      // 0..3 -> 16 keys

    // load Q tile: q = tid&63, d chunk = (tid>>6)*16
    {
        const int qq = tid & 63;
        const int d0 = (tid >> 6) * 16;
        const float* qp = Q + rowbase + (q0 + qq) * C_ + d0;
#pragma unroll
        for (int j = 0; j < 4; ++j) {
            float4 v = *(const float4*)(qp + j * 4);
            uint4 t;
            t.x = f2tf(v.x); t.y = f2tf(v.y); t.z = f2tf(v.z); t.w = f2tf(v.w);
            *(uint4*)&Qs[qq][d0 + j * 4] = t;
        }
    }

    float rmax[2][2];
    rmax[0][0] = rmax[0][1] = rmax[1][0] = rmax[1][1] = -1e30f;

    const int kn = tid & 63;           // key within tile
    const int kd0 = (tid >> 6) * 16;   // d chunk

    for (int nt = 0; nt < S_; nt += 64) {
        __syncthreads();
        // load K^T tile: Ks[d][key] (transposed scalar stores, conflict-free)
        const float* kp = K + rowbase + (nt + kn) * C_ + kd0;
#pragma unroll
        for (int j = 0; j < 4; ++j) {
            float4 v = *(const float4*)(kp + j * 4);
            Ks[kd0 + j * 4 + 0][kn] = f2tf(v.x);
            Ks[kd0 + j * 4 + 1][kn] = f2tf(v.y);
            Ks[kd0 + j * 4 + 2][kn] = f2tf(v.z);
            Ks[kd0 + j * 4 + 3][kn] = f2tf(v.w);
        }
        __syncthreads();

        float c[2][2][4];
#pragma unroll
        for (int i = 0; i < 2; ++i)
#pragma unroll
            for (int j = 0; j < 2; ++j)
#pragma unroll
                for (int r = 0; r < 4; ++r) c[i][j][r] = 0.f;

#pragma unroll
        for (int ks = 0; ks < 8; ++ks) {
            const int k0 = ks * 8;
            unsigned a[2][4];
#pragma unroll
            for (int m2 = 0; m2 < 2; ++m2) {
                const int mr = warpM * 32 + m2 * 16;
                a[m2][0] = Qs[mr + g][k0 + tig];
                a[m2][1] = Qs[mr + g + 8][k0 + tig];
                a[m2][2] = Qs[mr + g][k0 + tig + 4];
                a[m2][3] = Qs[mr + g + 8][k0 + tig + 4];
            }
#pragma unroll
            for (int j = 0; j < 2; ++j) {
                unsigned bb[2];
                const int nc = warpN * 16 + j * 8 + g;
                bb[0] = Ks[k0 + tig][nc];
                bb[1] = Ks[k0 + tig + 4][nc];
                MMA_TF32(c[0][j], a[0], bb);
                MMA_TF32(c[1][j], a[1], bb);
            }
        }
#pragma unroll
        for (int m2 = 0; m2 < 2; ++m2)
#pragma unroll
            for (int j = 0; j < 2; ++j) {
                rmax[m2][0] = fmaxf(rmax[m2][0], fmaxf(c[m2][j][0], c[m2][j][1]));
                rmax[m2][1] = fmaxf(rmax[m2][1], fmaxf(c[m2][j][2], c[m2][j][3]));
            }
    }

    // reduce over tig lanes (cols)
#pragma unroll
    for (int off = 1; off <= 2; off <<= 1)
#pragma unroll
        for (int m2 = 0; m2 < 2; ++m2)
#pragma unroll
            for (int r = 0; r < 2; ++r)
                rmax[m2][r] = fmaxf(rmax[m2][r],
                                    __shfl_xor_sync(0xffffffffu, rmax[m2][r], off));

    __syncthreads();
    if (tig == 0) {
#pragma unroll
        for (int m2 = 0; m2 < 2; ++m2)
#pragma unroll
            for (int r = 0; r < 2; ++r)
                buf[warpN][warpM * 32 + m2 * 16 + r * 8 + g] = rmax[m2][r];
    }
    __syncthreads();
    if (tid < 64) {
        float m = fmaxf(fmaxf(buf[0][tid], buf[1][tid]),
                        fmaxf(buf[2][tid], buf[3][tid]));
        m1[bh * S_ + q0 + tid] = m * 0.125f;
    }
}

// ============================================================================
// V column sums per (b,h): vs[bh][d] = sum_k V[k][d]
// ============================================================================
__global__ __launch_bounds__(256) void vsum_k(
    const float* __restrict__ V, float* __restrict__ vs)
{
    __shared__ float red[4][64];
    const int bh = blockIdx.x;
    const int b = bh >> 4, h = bh & 15;
    const int tid = threadIdx.x;
    const int d = tid & 63, g = tid >> 6;
    const float* p = V + (b * S_) * C_ + h * DH_ + d;
    float s = 0.f;
    for (int k = g; k < S_; k += 4) s += p[k * C_];
    red[g][d] = s;
    __syncthreads();
    if (tid < 64)
        vs[bh * 64 + tid] = red[0][tid] + red[1][tid] + red[2][tid] + red[3][tid];
}

// ============================================================================
// Banded attention, 2 threads per query (d-split), predicated band weight.
// out[q] = (sum_band (e^{t}-1) v + vsum) / (S + sum_band (e^{t}-1)),
// t = exp(s/8 - m1_q).
// ============================================================================
__global__ __launch_bounds__(128) void band_attn(
    const float* __restrict__ Q, const float* __restrict__ K,
    const float* __restrict__ V, const float* __restrict__ m1,
    const float* __restrict__ vs, float* __restrict__ O)
{
    __shared__ float Ks[64][64];
    __shared__ float Vs[64][64];

    const int bh = blockIdx.y;
    const int b = bh >> 4, h = bh & 15;
    const int q0 = blockIdx.x * 64;
    const int tid = threadIdx.x;
    const int qi = tid >> 1;        // 0..63
    const int ht = tid & 1;         // d-half
    const int q = q0 + qi;
    const int rowbase = (b * S_) * C_ + h * DH_;

    float qv[32];
    const float* qptr = Q + rowbase + q * C_ + ht * 32;
#pragma unroll
    for (int j = 0; j < 32; j += 4)
        *(float4*)&qv[j] = *(const float4*)(qptr + j);

    const float m1q = m1[bh * S_ + q];

    float acc[32];
#pragma unroll
    for (int j = 0; j < 32; ++j) acc[j] = 0.f;
    float Z = 0.f;

    const int klo  = (q0 >= 128) ? q0 - 128 : 0;       // 64-aligned
    const int kend = (q0 + 192 < S_) ? q0 + 192 : S_;

    for (int kt = klo; kt < kend; kt += 64) {
        __syncthreads();
#pragma unroll
        for (int u = 0; u < 8; ++u) {
            int f = tid + 128 * u;      // 0..1023 float4 slots
            int kk = f >> 4;            // 0..63
            int d4 = (f & 15) * 4;
            int gg = rowbase + (kt + kk) * C_ + d4;
            *(float4*)&Ks[kk][d4] = *(const float4*)(K + gg);
            *(float4*)&Vs[kk][d4] = *(const float4*)(V + gg);
        }
        __syncthreads();

#pragma unroll 4
        for (int kk = 0; kk < 64; ++kk) {
            float s = 0.f;
#pragma unroll
            for (int j = 0; j < 32; j += 4) {
                float4 kv = *(const float4*)&Ks[kk][ht * 32 + j];
                s = fmaf(qv[j + 0], kv.x, s);
                s = fmaf(qv[j + 1], kv.y, s);
                s = fmaf(qv[j + 2], kv.z, s);
                s = fmaf(qv[j + 3], kv.w, s);
            }
            s += __shfl_xor_sync(0xffffffffu, s, 1);
            float t = __expf(s * 0.125f - m1q);   // t in (0,~1], no overflow
            float w = __expf(t) - 1.0f;
            int d = kt + kk - q;
            if (d < -128 || d > 127) w = 0.f;     // outside band
            Z += w;
#pragma unroll
            for (int j = 0; j < 32; j += 4) {
                float4 vv = *(const float4*)&Vs[kk][ht * 32 + j];
                acc[j + 0] = fmaf(w, vv.x, acc[j + 0]);
                acc[j + 1] = fmaf(w, vv.y, acc[j + 1]);
                acc[j + 2] = fmaf(w, vv.z, acc[j + 2]);
                acc[j + 3] = fmaf(w, vv.w, acc[j + 3]);
            }
        }
    }

    const float inv = 1.0f / ((float)S_ + Z);
    const float* vsp = vs + bh * 64 + ht * 32;
    float* op = O + rowbase + q * C_ + ht * 32;
#pragma unroll
    for (int j = 0; j < 32; j += 4) {
        float4 vv = *(const float4*)(vsp + j);
        float4 o;
        o.x = (acc[j + 0] + vv.x) * inv;
        o.y = (acc[j + 1] + vv.y) * inv;
        o.z = (acc[j + 2] + vv.z) * inv;
        o.w = (acc[j + 3] + vv.w) * inv;
        *(float4*)(op + j) = o;
    }
}

// ============================================================================
extern "C" void kernel_launch(void* const* d_in, const int* in_sizes, int n_in,
                              void* d_out, int out_size)
{
    (void)in_sizes; (void)n_in; (void)out_size;
    const float* x  = (const float*)d_in[0];
    const float* Wq = (const float*)d_in[1];
    const float* Wk = (const float*)d_in[2];
    const float* Wv = (const float*)d_in[3];
    const float* Wo = (const float*)d_in[4];
    float* out = (float*)d_out;

    float *Qp, *Kp, *Vp, *Ap, *m1p, *vsp;
    cudaGetSymbolAddress((void**)&Qp,  g_Q);
    cudaGetSymbolAddress((void**)&Kp,  g_K);
    cudaGetSymbolAddress((void**)&Vp,  g_V);
    cudaGetSymbolAddress((void**)&Ap,  g_A);
    cudaGetSymbolAddress((void**)&m1p, g_m1);
    cudaGetSymbolAddress((void**)&vsp, g_vs);

    dim3 gg(C_ / 128, M_ / 128);            // (8, 32)
    tgemm<<<gg, 256>>>(x, Wq, Qp, M_, C_, C_);
    tgemm<<<gg, 256>>>(x, Wk, Kp, M_, C_, C_);
    tgemm<<<gg, 256>>>(x, Wv, Vp, M_, C_, C_);

    score_max_t<<<dim3(S_ / 64, B_ * H_), 256>>>(Qp, Kp, m1p);
    vsum_k<<<B_ * H_, 256>>>(Vp, vsp);
    band_attn<<<dim3(S_ / 64, B_ * H_), 128>>>(Qp, Kp, Vp, m1p, vsp, Ap);

    tgemm<<<gg, 256>>>(Ap, Wo, out, M_, C_, C_);
}

// round 4
// speedup vs baseline: 2.2304x; 1.1302x over previous
#include <cuda_runtime.h>
#include <math.h>

#define B_   2
#define S_   2048
#define C_   1024
#define H_   16
#define DH_  64
#define M_   (B_ * S_)       // 4096 rows

// ---- scratch (device globals; no allocation allowed) ----
__device__ float g_Q[M_ * C_];
__device__ float g_K[M_ * C_];
__device__ float g_V[M_ * C_];
__device__ float g_A[M_ * C_];           // attention output (pre out-proj)
__device__ float g_m1[B_ * H_ * S_];     // full-row max of scores (already /8)
__device__ float g_vs[B_ * H_ * DH_];    // sum over all keys of V per (b,h)

__device__ __forceinline__ unsigned f2tf(float x) {
    unsigned r;
    asm("cvt.rna.tf32.f32 %0, %1;" : "=r"(r) : "f"(x));
    return r;
}

#define MMA_TF32(c, a, b)                                                     \
    asm volatile(                                                             \
        "mma.sync.aligned.m16n8k8.row.col.f32.tf32.tf32.f32 "                 \
        "{%0,%1,%2,%3},{%4,%5,%6,%7},{%8,%9},{%0,%1,%2,%3};"                  \
        : "+f"((c)[0]), "+f"((c)[1]), "+f"((c)[2]), "+f"((c)[3])              \
        : "r"((a)[0]), "r"((a)[1]), "r"((a)[2]), "r"((a)[3]),                 \
          "r"((b)[0]), "r"((b)[1]))

// ============================================================================
// tf32 tensor-core GEMM: C = A[M,K] @ B[K,N], 128x128x32 block tile,
// 8 warps (4x2), warp tile 32x64. B smem xor-swizzled (conflict-free loads).
// ============================================================================
__global__ __launch_bounds__(256) void tgemm(
    const float* __restrict__ A, const float* __restrict__ Bm,
    float* __restrict__ C, int M, int N, int K)
{
    __shared__ unsigned As[128][36];   // [m][k] tf32 (pad 36 -> g*4+tig banks)
    __shared__ unsigned Bs[32][128];   // [k][n] tf32, col ^ ((k&3)<<3)

    const int tid = threadIdx.x;
    const int bm = blockIdx.y * 128;
    const int bn = blockIdx.x * 128;

    const int wid  = tid >> 5;
    const int lane = tid & 31;
    const int g    = lane >> 2;
    const int tig  = lane & 3;
    const int warpM = wid >> 1;      // 0..3
    const int warpN = wid & 1;       // 0..1
    const unsigned swz = tig << 3;

    const int a_m  = tid >> 1;                 // 0..127
    const int a_k0 = (tid & 1) * 16;           // 0 or 16
    const int b_k  = tid >> 3;                 // 0..31
    const int b_n0 = (tid & 7) * 16;           // 0..112
    const unsigned bswz = (b_k & 3) << 3;

    const float* Ap = A + (bm + a_m) * K + a_k0;
    const float* Bp = Bm + b_k * N + bn + b_n0;

    float c[2][8][4];
#pragma unroll
    for (int i = 0; i < 2; ++i)
#pragma unroll
        for (int j = 0; j < 8; ++j)
#pragma unroll
            for (int r = 0; r < 4; ++r) c[i][j][r] = 0.f;

    float4 av[4], bv[4];
#pragma unroll
    for (int j = 0; j < 4; ++j) {
        av[j] = *(const float4*)(Ap + j * 4);
        bv[j] = *(const float4*)(Bp + j * 4);
    }

    for (int kt = 0; kt < K; kt += 32) {
#pragma unroll
        for (int j = 0; j < 4; ++j) {
            uint4 ta, tb;
            ta.x = f2tf(av[j].x); ta.y = f2tf(av[j].y);
            ta.z = f2tf(av[j].z); ta.w = f2tf(av[j].w);
            tb.x = f2tf(bv[j].x); tb.y = f2tf(bv[j].y);
            tb.z = f2tf(bv[j].z); tb.w = f2tf(bv[j].w);
            *(uint4*)&As[a_m][a_k0 + j * 4] = ta;
            *(uint4*)&Bs[b_k][(b_n0 + j * 4) ^ bswz] = tb;
        }
        __syncthreads();

        if (kt + 32 < K) {
#pragma unroll
            for (int j = 0; j < 4; ++j) {
                av[j] = *(const float4*)(Ap + kt + 32 + j * 4);
                bv[j] = *(const float4*)(Bp + (kt + 32) * N + j * 4);
            }
        }

#pragma unroll
        for (int ks = 0; ks < 4; ++ks) {
            const int k0 = ks * 8;
            unsigned a[2][4];
#pragma unroll
            for (int m2 = 0; m2 < 2; ++m2) {
                const int mr = warpM * 32 + m2 * 16;
                a[m2][0] = As[mr + g][k0 + tig];
                a[m2][1] = As[mr + g + 8][k0 + tig];
                a[m2][2] = As[mr + g][k0 + tig + 4];
                a[m2][3] = As[mr + g + 8][k0 + tig + 4];
            }
#pragma unroll
            for (int j = 0; j < 8; ++j) {
                unsigned b[2];
                const unsigned nc = (unsigned)(warpN * 64 + j * 8 + g) ^ swz;
                b[0] = Bs[k0 + tig][nc];
                b[1] = Bs[k0 + tig + 4][nc];
                MMA_TF32(c[0][j], a[0], b);
                MMA_TF32(c[1][j], a[1], b);
            }
        }
        __syncthreads();
    }

#pragma unroll
    for (int m2 = 0; m2 < 2; ++m2) {
#pragma unroll
        for (int j = 0; j < 8; ++j) {
            const int row = bm + warpM * 32 + m2 * 16 + g;
            const int col = bn + warpN * 64 + j * 8 + 2 * tig;
            *(float2*)&C[row * N + col]       = make_float2(c[m2][j][0], c[m2][j][1]);
            *(float2*)&C[(row + 8) * N + col] = make_float2(c[m2][j][2], c[m2][j][3]);
        }
    }
}

// Fused QKV projections: blockIdx.z selects weight/output.
__global__ __launch_bounds__(256) void tgemm_qkv(
    const float* __restrict__ A,
    const float* __restrict__ W0, const float* __restrict__ W1,
    const float* __restrict__ W2,
    float* __restrict__ C0, float* __restrict__ C1, float* __restrict__ C2)
{
    const int z = blockIdx.z;
    const float* Bm = (z == 0) ? W0 : ((z == 1) ? W1 : W2);
    float* C = (z == 0) ? C0 : ((z == 1) ? C1 : C2);

    // inline the same body via a device call would duplicate; just call tgemm's
    // logic by re-launching is not possible -> duplicate minimal: use tgemm as
    // __device__? Simplest: replicate via macro-free direct call:
    // (kept as a thin wrapper: identical code path)
    extern __shared__ char _dummy[]; (void)_dummy;
    // --- body identical to tgemm ---
    __shared__ unsigned As[128][36];
    __shared__ unsigned Bs[32][128];

    const int tid = threadIdx.x;
    const int bm = blockIdx.y * 128;
    const int bn = blockIdx.x * 128;
    const int M = M_, N = C_, K = C_;

    const int wid  = tid >> 5;
    const int lane = tid & 31;
    const int g    = lane >> 2;
    const int tig  = lane & 3;
    const int warpM = wid >> 1;
    const int warpN = wid & 1;
    const unsigned swz = tig << 3;

    const int a_m  = tid >> 1;
    const int a_k0 = (tid & 1) * 16;
    const int b_k  = tid >> 3;
    const int b_n0 = (tid & 7) * 16;
    const unsigned bswz = (b_k & 3) << 3;

    const float* Ap = A + (bm + a_m) * K + a_k0;
    const float* Bp = Bm + b_k * N + bn + b_n0;

    float c[2][8][4];
#pragma unroll
    for (int i = 0; i < 2; ++i)
#pragma unroll
        for (int j = 0; j < 8; ++j)
#pragma unroll
            for (int r = 0; r < 4; ++r) c[i][j][r] = 0.f;

    float4 av[4], bv[4];
#pragma unroll
    for (int j = 0; j < 4; ++j) {
        av[j] = *(const float4*)(Ap + j * 4);
        bv[j] = *(const float4*)(Bp + j * 4);
    }

    for (int kt = 0; kt < K; kt += 32) {
#pragma unroll
        for (int j = 0; j < 4; ++j) {
            uint4 ta, tb;
            ta.x = f2tf(av[j].x); ta.y = f2tf(av[j].y);
            ta.z = f2tf(av[j].z); ta.w = f2tf(av[j].w);
            tb.x = f2tf(bv[j].x); tb.y = f2tf(bv[j].y);
            tb.z = f2tf(bv[j].z); tb.w = f2tf(bv[j].w);
            *(uint4*)&As[a_m][a_k0 + j * 4] = ta;
            *(uint4*)&Bs[b_k][(b_n0 + j * 4) ^ bswz] = tb;
        }
        __syncthreads();

        if (kt + 32 < K) {
#pragma unroll
            for (int j = 0; j < 4; ++j) {
                av[j] = *(const float4*)(Ap + kt + 32 + j * 4);
                bv[j] = *(const float4*)(Bp + (kt + 32) * N + j * 4);
            }
        }

#pragma unroll
        for (int ks = 0; ks < 4; ++ks) {
            const int k0 = ks * 8;
            unsigned a[2][4];
#pragma unroll
            for (int m2 = 0; m2 < 2; ++m2) {
                const int mr = warpM * 32 + m2 * 16;
                a[m2][0] = As[mr + g][k0 + tig];
                a[m2][1] = As[mr + g + 8][k0 + tig];
                a[m2][2] = As[mr + g][k0 + tig + 4];
                a[m2][3] = As[mr + g + 8][k0 + tig + 4];
            }
#pragma unroll
            for (int j = 0; j < 8; ++j) {
                unsigned b[2];
                const unsigned nc = (unsigned)(warpN * 64 + j * 8 + g) ^ swz;
                b[0] = Bs[k0 + tig][nc];
                b[1] = Bs[k0 + tig + 4][nc];
                MMA_TF32(c[0][j], a[0], b);
                MMA_TF32(c[1][j], a[1], b);
            }
        }
        __syncthreads();
    }

#pragma unroll
    for (int m2 = 0; m2 < 2; ++m2) {
#pragma unroll
        for (int j = 0; j < 8; ++j) {
            const int row = bm + warpM * 32 + m2 * 16 + g;
            const int col = bn + warpN * 64 + j * 8 + 2 * tig;
            *(float2*)&C[row * N + col]       = make_float2(c[m2][j][0], c[m2][j][1]);
            *(float2*)&C[(row + 8) * N + col] = make_float2(c[m2][j][2], c[m2][j][3]);
        }
    }
    (void)M;
}

// ============================================================================
// tf32 score row-max: m1[bh][q] = max_k (q.k)/8.
// S[key][query] = K @ Q^T: A = K tile (natural row-major), B = Q^T (natural
// row-major Q). Q fragments hoisted to registers for the whole kernel.
// Double-buffered K tiles, 1 sync per 64-key tile. Max over rows (keys).
// 8 warps: warpM=wid&3 (16 keys), warpN=wid>>2 (32 queries, 4 n-atoms).
// ============================================================================
__global__ __launch_bounds__(256, 2) void score_max_t(
    const float* __restrict__ Q, const float* __restrict__ K,
    float* __restrict__ m1)
{
    __shared__ unsigned Ks[2][64][68];   // pad 68: row*68 ≡ row*4 (mod 32)
    __shared__ float buf[4][64];

    const int bh = blockIdx.y;
    const int b = bh >> 4, h = bh & 15;
    const int q0 = blockIdx.x * 64;
    const int tid = threadIdx.x;
    const int rowbase = (b * S_) * C_ + h * DH_;

    const int wid  = tid >> 5;
    const int lane = tid & 31;
    const int g    = lane >> 2;
    const int tig  = lane & 3;
    const int warpM = wid & 3;        // 0..3 -> keys warpM*16..+15
    const int warpN = wid >> 2;       // 0..1 -> queries warpN*32..+31

    const int ld_r = tid >> 2;          // 0..63 tile row
    const int ld_c = (tid & 3) * 4;     // col base (coalesced float4)

    // ---- stage Q tile into Ks[0], extract B fragments to registers ----
    {
        const float* qp = Q + rowbase + (q0 + ld_r) * C_ + ld_c;
#pragma unroll
        for (int j = 0; j < 4; ++j) {
            float4 v = *(const float4*)(qp + j * 16);
            Ks[0][ld_r][ld_c + j * 16 + 0] = f2tf(v.x);
            Ks[0][ld_r][ld_c + j * 16 + 1] = f2tf(v.y);
            Ks[0][ld_r][ld_c + j * 16 + 2] = f2tf(v.z);
            Ks[0][ld_r][ld_c + j * 16 + 3] = f2tf(v.w);
        }
    }
    __syncthreads();

    unsigned bq[4][8][2];
#pragma unroll
    for (int na = 0; na < 4; ++na) {
        const int nc = warpN * 32 + na * 8 + g;
#pragma unroll
        for (int ks = 0; ks < 8; ++ks) {
            bq[na][ks][0] = Ks[0][nc][ks * 8 + tig];
            bq[na][ks][1] = Ks[0][nc][ks * 8 + tig + 4];
        }
    }
    __syncthreads();

    float rmax[4][2];
#pragma unroll
    for (int na = 0; na < 4; ++na) { rmax[na][0] = -1e30f; rmax[na][1] = -1e30f; }

    // prefetch K tile 0
    float4 kv[4];
    {
        const float* kp = K + rowbase + ld_r * C_ + ld_c;
#pragma unroll
        for (int j = 0; j < 4; ++j) kv[j] = *(const float4*)(kp + j * 16);
    }

    for (int t = 0; t < S_ / 64; ++t) {
        const int cur = t & 1;
#pragma unroll
        for (int j = 0; j < 4; ++j) {
            Ks[cur][ld_r][ld_c + j * 16 + 0] = f2tf(kv[j].x);
            Ks[cur][ld_r][ld_c + j * 16 + 1] = f2tf(kv[j].y);
            Ks[cur][ld_r][ld_c + j * 16 + 2] = f2tf(kv[j].z);
            Ks[cur][ld_r][ld_c + j * 16 + 3] = f2tf(kv[j].w);
        }
        __syncthreads();

        if (t + 1 < S_ / 64) {
            const float* kp = K + rowbase + ((t + 1) * 64 + ld_r) * C_ + ld_c;
#pragma unroll
            for (int j = 0; j < 4; ++j) kv[j] = *(const float4*)(kp + j * 16);
        }

        float c[4][4];
#pragma unroll
        for (int na = 0; na < 4; ++na)
#pragma unroll
            for (int r = 0; r < 4; ++r) c[na][r] = 0.f;

        const int mr = warpM * 16;
#pragma unroll
        for (int ks = 0; ks < 8; ++ks) {
            const int k0 = ks * 8;
            unsigned a[4];
            a[0] = Ks[cur][mr + g][k0 + tig];
            a[1] = Ks[cur][mr + g + 8][k0 + tig];
            a[2] = Ks[cur][mr + g][k0 + tig + 4];
            a[3] = Ks[cur][mr + g + 8][k0 + tig + 4];
#pragma unroll
            for (int na = 0; na < 4; ++na)
                MMA_TF32(c[na], a, bq[na][ks]);
        }

        // rows = keys -> max over rows; cols = queries
#pragma unroll
        for (int na = 0; na < 4; ++na) {
            rmax[na][0] = fmaxf(rmax[na][0], fmaxf(c[na][0], c[na][2]));
            rmax[na][1] = fmaxf(rmax[na][1], fmaxf(c[na][1], c[na][3]));
        }
    }

    // reduce over g lanes (xor 4,8,16 keeps tig)
#pragma unroll
    for (int off = 4; off <= 16; off <<= 1)
#pragma unroll
        for (int na = 0; na < 4; ++na) {
            rmax[na][0] = fmaxf(rmax[na][0], __shfl_xor_sync(0xffffffffu, rmax[na][0], off));
            rmax[na][1] = fmaxf(rmax[na][1], __shfl_xor_sync(0xffffffffu, rmax[na][1], off));
        }

    if (g == 0) {
#pragma unroll
        for (int na = 0; na < 4; ++na) {
            buf[warpM][warpN * 32 + na * 8 + tig * 2 + 0] = rmax[na][0];
            buf[warpM][warpN * 32 + na * 8 + tig * 2 + 1] = rmax[na][1];
        }
    }
    __syncthreads();
    if (tid < 64) {
        float m = fmaxf(fmaxf(buf[0][tid], buf[1][tid]),
                        fmaxf(buf[2][tid], buf[3][tid]));
        m1[bh * S_ + q0 + tid] = m * 0.125f;
    }
}

// ============================================================================
// V column sums per (b,h): vs[bh][d] = sum_k V[k][d]
// ============================================================================
__global__ __launch_bounds__(256) void vsum_k(
    const float* __restrict__ V, float* __restrict__ vs)
{
    __shared__ float red[4][64];
    const int bh = blockIdx.x;
    const int b = bh >> 4, h = bh & 15;
    const int tid = threadIdx.x;
    const int d = tid & 63, g = tid >> 6;
    const float* p = V + (b * S_) * C_ + h * DH_ + d;
    float s = 0.f;
    for (int k = g; k < S_; k += 4) s += p[k * C_];
    red[g][d] = s;
    __syncthreads();
    if (tid < 64)
        vs[bh * 64 + tid] = red[0][tid] + red[1][tid] + red[2][tid] + red[3][tid];
}

// ============================================================================
// Banded attention, 2 threads per query (d-split), predicated band weight.
// ============================================================================
__global__ __launch_bounds__(128) void band_attn(
    const float* __restrict__ Q, const float* __restrict__ K,
    const float* __restrict__ V, const float* __restrict__ m1,
    const float* __restrict__ vs, float* __restrict__ O)
{
    __shared__ float Ks[64][64];
    __shared__ float Vs[64][64];

    const int bh = blockIdx.y;
    const int b = bh >> 4, h = bh & 15;
    const int q0 = blockIdx.x * 64;
    const int tid = threadIdx.x;
    const int qi = tid >> 1;
    const int ht = tid & 1;
    const int q = q0 + qi;
    const int rowbase = (b * S_) * C_ + h * DH_;

    float qv[32];
    const float* qptr = Q + rowbase + q * C_ + ht * 32;
#pragma unroll
    for (int j = 0; j < 32; j += 4)
        *(float4*)&qv[j] = *(const float4*)(qptr + j);

    const float m1q = m1[bh * S_ + q];

    float acc[32];
#pragma unroll
    for (int j = 0; j < 32; ++j) acc[j] = 0.f;
    float Z = 0.f;

    const int klo  = (q0 >= 128) ? q0 - 128 : 0;
    const int kend = (q0 + 192 < S_) ? q0 + 192 : S_;

    for (int kt = klo; kt < kend; kt += 64) {
        __syncthreads();
#pragma unroll
        for (int u = 0; u < 8; ++u) {
            int f = tid + 128 * u;
            int kk = f >> 4;
            int d4 = (f & 15) * 4;
            int gg = rowbase + (kt + kk) * C_ + d4;
            *(float4*)&Ks[kk][d4] = *(const float4*)(K + gg);
            *(float4*)&Vs[kk][d4] = *(const float4*)(V + gg);
        }
        __syncthreads();

#pragma unroll 4
        for (int kk = 0; kk < 64; ++kk) {
            float s = 0.f;
#pragma unroll
            for (int j = 0; j < 32; j += 4) {
                float4 kvv = *(const float4*)&Ks[kk][ht * 32 + j];
                s = fmaf(qv[j + 0], kvv.x, s);
                s = fmaf(qv[j + 1], kvv.y, s);
                s = fmaf(qv[j + 2], kvv.z, s);
                s = fmaf(qv[j + 3], kvv.w, s);
            }
            s += __shfl_xor_sync(0xffffffffu, s, 1);
            float t = __expf(s * 0.125f - m1q);
            float w = __expf(t) - 1.0f;
            int d = kt + kk - q;
            if (d < -128 || d > 127) w = 0.f;
            Z += w;
#pragma unroll
            for (int j = 0; j < 32; j += 4) {
                float4 vv = *(const float4*)&Vs[kk][ht * 32 + j];
                acc[j + 0] = fmaf(w, vv.x, acc[j + 0]);
                acc[j + 1] = fmaf(w, vv.y, acc[j + 1]);
                acc[j + 2] = fmaf(w, vv.z, acc[j + 2]);
                acc[j + 3] = fmaf(w, vv.w, acc[j + 3]);
            }
        }
    }

    const float inv = 1.0f / ((float)S_ + Z);
    const float* vsp = vs + bh * 64 + ht * 32;
    float* op = O + rowbase + q * C_ + ht * 32;
#pragma unroll
    for (int j = 0; j < 32; j += 4) {
        float4 vv = *(const float4*)(vsp + j);
        float4 o;
        o.x = (acc[j + 0] + vv.x) * inv;
        o.y = (acc[j + 1] + vv.y) * inv;
        o.z = (acc[j + 2] + vv.z) * inv;
        o.w = (acc[j + 3] + vv.w) * inv;
        *(float4*)(op + j) = o;
    }
}

// ============================================================================
extern "C" void kernel_launch(void* const* d_in, const int* in_sizes, int n_in,
                              void* d_out, int out_size)
{
    (void)in_sizes; (void)n_in; (void)out_size;
    const float* x  = (const float*)d_in[0];
    const float* Wq = (const float*)d_in[1];
    const float* Wk = (const float*)d_in[2];
    const float* Wv = (const float*)d_in[3];
    const float* Wo = (const float*)d_in[4];
    float* out = (float*)d_out;

    float *Qp, *Kp, *Vp, *Ap, *m1p, *vsp;
    cudaGetSymbolAddress((void**)&Qp,  g_Q);
    cudaGetSymbolAddress((void**)&Kp,  g_K);
    cudaGetSymbolAddress((void**)&Vp,  g_V);
    cudaGetSymbolAddress((void**)&Ap,  g_A);
    cudaGetSymbolAddress((void**)&m1p, g_m1);
    cudaGetSymbolAddress((void**)&vsp, g_vs);

    dim3 gq(C_ / 128, M_ / 128, 3);         // (8, 32, 3)
    tgemm_qkv<<<gq, 256>>>(x, Wq, Wk, Wv, Qp, Kp, Vp);

    score_max_t<<<dim3(S_ / 64, B_ * H_), 256>>>(Qp, Kp, m1p);
    vsum_k<<<B_ * H_, 256>>>(Vp, vsp);
    band_attn<<<dim3(S_ / 64, B_ * H_), 128>>>(Qp, Kp, Vp, m1p, vsp, Ap);

    dim3 gg(C_ / 128, M_ / 128);            // (8, 32)
    tgemm<<<gg, 256>>>(Ap, Wo, out, M_, C_, C_);
}